// round 1
// baseline (speedup 1.0000x reference)
#include <cuda_runtime.h>

#define NN   100000      // nodes
#define NPAD 100096      // 782 * 128
#define NE   1600000     // edges
#define H    128
#define NG   2000        // graphs
#define NS   200         // sets
#define NC   10          // classes

// ---------------- scratch (static device globals; no allocation) -------------
__device__ __align__(16) float g_deg [NN];
__device__ __align__(16) float g_dinv[NN];
__device__ __align__(16) float g_norm[NE];
__device__ __align__(16) float g_hW [(size_t)NPAD * H];   // GEMM output
__device__ __align__(16) float g_acc[(size_t)NPAD * H];   // scatter accumulator / layer io
__device__ __align__(16) float g_gemb[NG * H];
__device__ __align__(16) float g_agg [NS * H];

// ---------------- degree / normalization -------------------------------------
__global__ void k_deg_init() {
    int i = blockIdx.x * 256 + threadIdx.x;
    if (i < NN) g_deg[i] = 1.0f;                 // self-loop contributes 1
}
__global__ void k_deg_count(const int* __restrict__ dst) {
    int e = blockIdx.x * 256 + threadIdx.x;
    if (e < NE) atomicAdd(&g_deg[dst[e]], 1.0f); // integer-valued: exact in fp32
}
__global__ void k_dinv() {
    int i = blockIdx.x * 256 + threadIdx.x;
    if (i < NN) g_dinv[i] = rsqrtf(g_deg[i]);
}
__global__ void k_norm(const int* __restrict__ src, const int* __restrict__ dst) {
    int e = blockIdx.x * 256 + threadIdx.x;
    if (e < NE) g_norm[e] = g_dinv[src[e]] * g_dinv[dst[e]];
}

// ---------------- zero fills --------------------------------------------------
__global__ void k_zero_acc() {
    int i = blockIdx.x * 256 + threadIdx.x;
    if (i < NPAD * (H / 4)) ((float4*)g_acc)[i] = make_float4(0.f, 0.f, 0.f, 0.f);
}
__global__ void k_zero_agg() {
    int i = blockIdx.x * 256 + threadIdx.x;
    if (i < NS * H) g_agg[i] = 0.f;
}

// ---------------- SGEMM: C(g_hW) = A[nrows,128] @ B[128,128] -----------------
// BM=128, BN=128, BK=16, 256 threads, 8x8 register tile per thread.
__global__ __launch_bounds__(256) void k_gemm(const float* __restrict__ Ax,
                                              const float* __restrict__ B,
                                              int use_x, int nrows) {
    __shared__ float As[16][128];   // [k][row]
    __shared__ float Bs[16][128];   // [k][col]
    const float* A = use_x ? Ax : (const float*)g_acc;

    float acc[8][8];
#pragma unroll
    for (int m = 0; m < 8; m++)
#pragma unroll
        for (int n = 0; n < 8; n++) acc[m][n] = 0.f;

    const int tid = threadIdx.x;
    const int tx = tid & 15;        // 0..15 -> cols tx*8..tx*8+7
    const int ty = tid >> 4;        // 0..15 -> rows ty*8..ty*8+7
    const int rowBase = blockIdx.x * 128;

    for (int k0 = 0; k0 < 128; k0 += 16) {
        // load A tile 128x16 (512 float4, 2 per thread), transposed into As
#pragma unroll
        for (int i = 0; i < 2; i++) {
            int f = tid + i * 256;
            int r = f >> 2;             // 0..127
            int c = (f & 3) * 4;        // 0,4,8,12
            int gr = rowBase + r;
            float4 v = make_float4(0.f, 0.f, 0.f, 0.f);
            if (gr < nrows) v = *(const float4*)(A + (size_t)gr * H + k0 + c);
            As[c + 0][r] = v.x; As[c + 1][r] = v.y;
            As[c + 2][r] = v.z; As[c + 3][r] = v.w;
        }
        // load B tile 16x128
#pragma unroll
        for (int i = 0; i < 2; i++) {
            int f = tid + i * 256;
            int r = f >> 5;             // 0..15
            int c = (f & 31) * 4;       // 0..124
            *(float4*)&Bs[r][c] = *(const float4*)(B + (size_t)(k0 + r) * H + c);
        }
        __syncthreads();

#pragma unroll
        for (int k = 0; k < 16; k++) {
            float rm[8], rn[8];
#pragma unroll
            for (int m = 0; m < 8; m++) rm[m] = As[k][ty * 8 + m];
#pragma unroll
            for (int n = 0; n < 8; n++) rn[n] = Bs[k][tx * 8 + n];
#pragma unroll
            for (int m = 0; m < 8; m++)
#pragma unroll
                for (int n = 0; n < 8; n++) acc[m][n] += rm[m] * rn[n];
        }
        __syncthreads();
    }

#pragma unroll
    for (int m = 0; m < 8; m++) {
        int gr = rowBase + ty * 8 + m;
        if (gr < nrows) {
#pragma unroll
            for (int n = 0; n < 8; n += 4) {
                *(float4*)(g_hW + (size_t)gr * H + tx * 8 + n) =
                    make_float4(acc[m][n], acc[m][n + 1], acc[m][n + 2], acc[m][n + 3]);
            }
        }
    }
}

// ---------------- edge scatter: acc[dst] += norm * hW[src] -------------------
// one warp per edge; each lane handles 4 consecutive dims (float4 gather).
__global__ __launch_bounds__(256) void k_scatter(const int* __restrict__ src,
                                                 const int* __restrict__ dst) {
    int idx = blockIdx.x * 256 + threadIdx.x;
    int e = idx >> 5;
    if (e >= NE) return;
    int q = idx & 31;
    int s = __ldg(src + e);
    int t = __ldg(dst + e);
    float nm = __ldg(g_norm + e);
    float4 v = __ldg((const float4*)(g_hW + (size_t)s * H) + q);
    float* p = g_acc + (size_t)t * H + q * 4;
    atomicAdd(p + 0, nm * v.x);
    atomicAdd(p + 1, nm * v.y);
    atomicAdd(p + 2, nm * v.z);
    atomicAdd(p + 3, nm * v.w);
}

// ---------------- epilogue: acc = relu(acc + dinv^2*hW + b) (self-loop + bias)
__global__ void k_epi(const float* __restrict__ b) {
    int idx = blockIdx.x * 256 + threadIdx.x;
    int i = idx >> 5;
    if (i >= NN) return;
    int q = idx & 31;
    float di = g_dinv[i];
    float d2 = di * di;
    size_t o = (size_t)i * 32 + q;
    float4 a = ((const float4*)g_acc)[o];
    float4 w = ((const float4*)g_hW)[o];
    float4 bb = __ldg((const float4*)b + q);
    float4 r;
    r.x = fmaxf(a.x + d2 * w.x + bb.x, 0.f);
    r.y = fmaxf(a.y + d2 * w.y + bb.y, 0.f);
    r.z = fmaxf(a.z + d2 * w.z + bb.z, 0.f);
    r.w = fmaxf(a.w + d2 * w.w + bb.w, 0.f);
    ((float4*)g_acc)[o] = r;
}

// ---------------- mean pool per graph (batch is sorted) ----------------------
__device__ __forceinline__ int lower_bound_i(const int* a, int n, int v) {
    int lo = 0, hi = n;
    while (lo < hi) { int m = (lo + hi) >> 1; if (a[m] < v) lo = m + 1; else hi = m; }
    return lo;
}
__global__ void k_pool(const int* __restrict__ batch) {
    int g = blockIdx.x, d = threadIdx.x;
    __shared__ int lohi[2];
    if (d == 0) lohi[0] = lower_bound_i(batch, NN, g);
    if (d == 1) lohi[1] = lower_bound_i(batch, NN, g + 1);
    __syncthreads();
    int lo = lohi[0], hi = lohi[1];
    float s = 0.f;
    for (int i = lo; i < hi; i++) s += g_acc[(size_t)i * H + d];
    float c = (float)(hi - lo);
    g_gemb[g * H + d] = s / fmaxf(c, 1.f);
}

// ---------------- DeepSets psi + segment-sum into agg ------------------------
__global__ void k_psi(const int* __restrict__ setb,
                      const float* __restrict__ W1, const float* __restrict__ b1,
                      const float* __restrict__ W2, const float* __restrict__ b2) {
    int g = blockIdx.x, d = threadIdx.x;
    __shared__ float v[H], t[H];
    v[d] = g_gemb[g * H + d];
    __syncthreads();
    float s = b1[d];
#pragma unroll 8
    for (int k = 0; k < H; k++) s += v[k] * W1[k * H + d];
    t[d] = fmaxf(s, 0.f);
    __syncthreads();
    float s2 = b2[d];
#pragma unroll 8
    for (int k = 0; k < H; k++) s2 += t[k] * W2[k * H + d];
    atomicAdd(&g_agg[setb[g] * H + d], tanhf(s2));
}

// ---------------- phi head: out = relu(agg@phiW1+b1)@phiW2+b2 ----------------
__global__ void k_final(const float* __restrict__ W1, const float* __restrict__ b1,
                        const float* __restrict__ W2, const float* __restrict__ b2,
                        float* __restrict__ out) {
    int s = blockIdx.x, d = threadIdx.x;
    __shared__ float a[H], t[H];
    a[d] = g_agg[s * H + d];
    __syncthreads();
    float acc = b1[d];
#pragma unroll 8
    for (int k = 0; k < H; k++) acc += a[k] * W1[k * H + d];
    t[d] = fmaxf(acc, 0.f);
    __syncthreads();
    if (d < NC) {
        float o = b2[d];
#pragma unroll 8
        for (int k = 0; k < H; k++) o += t[k] * W2[k * NC + d];
        out[s * NC + d] = o;
    }
}

// ---------------- launch ------------------------------------------------------
extern "C" void kernel_launch(void* const* d_in, const int* in_sizes, int n_in,
                              void* d_out, int out_size) {
    const float* x     = (const float*)d_in[0];
    const int*   ei    = (const int*)  d_in[1];
    const int*   batch = (const int*)  d_in[2];
    const int*   setb  = (const int*)  d_in[3];
    const float* W1    = (const float*)d_in[4];
    const float* b1    = (const float*)d_in[5];
    const float* W2    = (const float*)d_in[6];
    const float* b2    = (const float*)d_in[7];
    const float* W3    = (const float*)d_in[8];
    const float* b3    = (const float*)d_in[9];
    const float* psiW1 = (const float*)d_in[10];
    const float* psib1 = (const float*)d_in[11];
    const float* psiW2 = (const float*)d_in[12];
    const float* psib2 = (const float*)d_in[13];
    const float* phiW1 = (const float*)d_in[14];
    const float* phib1 = (const float*)d_in[15];
    const float* phiW2 = (const float*)d_in[16];
    const float* phib2 = (const float*)d_in[17];
    float* out = (float*)d_out;

    const int* src = ei;          // edge_index[0]
    const int* dst = ei + NE;     // edge_index[1]

    k_deg_init <<<(NN + 255) / 256, 256>>>();
    k_deg_count<<<(NE + 255) / 256, 256>>>(dst);
    k_dinv     <<<(NN + 255) / 256, 256>>>();
    k_norm     <<<(NE + 255) / 256, 256>>>(src, dst);

    const float* Ws[3] = {W1, W2, W3};
    const float* bs[3] = {b1, b2, b3};
    for (int l = 0; l < 3; l++) {
        k_gemm    <<<NPAD / 128, 256>>>(x, Ws[l], l == 0 ? 1 : 0, NN);
        k_zero_acc<<<(NPAD * 32 + 255) / 256, 256>>>();
        k_scatter <<<(NE * 32 + 255) / 256, 256>>>(src, dst);
        k_epi     <<<(NN * 32 + 255) / 256, 256>>>(bs[l]);
    }

    k_pool    <<<NG, H>>>(batch);
    k_zero_agg<<<(NS * H + 255) / 256, 256>>>();
    k_psi     <<<NG, H>>>(setb, psiW1, psib1, psiW2, psib2);
    k_final   <<<NS, H>>>(phiW1, phib1, phiW2, phib2, out);
}

// round 2
// speedup vs baseline: 3.2900x; 3.2900x over previous
#include <cuda_runtime.h>

#define NN   100000      // nodes
#define NPAD 100096      // 782 * 128
#define NE   1600000     // edges
#define H    128
#define NG   2000        // graphs
#define NS   200         // sets
#define NC   10          // classes
#define NBLK 98          // ceil(NN/1024) scan blocks

// ---------------- scratch (static device globals; no allocation) -------------
__device__ __align__(16) int   g_cnt [NN];
__device__ __align__(16) int   g_tmp [NN];        // inclusive scan scratch
__device__ __align__(16) int   g_bsum[128];
__device__ __align__(16) int   g_row [NN + 1];    // CSR row offsets (by dst)
__device__ __align__(16) int   g_cur [NN];        // bucket cursors
__device__ __align__(16) int   g_csrc[NE];        // CSR src indices
__device__ __align__(16) float g_dinv[NN];
__device__ __align__(16) float g_hW [(size_t)NPAD * H];   // dinv-scaled GEMM out (hS)
__device__ __align__(16) float g_acc[(size_t)NPAD * H];   // layer output
__device__ __align__(16) float g_gemb[NG * H];
__device__ __align__(16) float g_agg [NS * H];

// ---------------- CSR build ---------------------------------------------------
__global__ void k_zero_cnt() {
    int i = blockIdx.x * 256 + threadIdx.x;
    if (i < NN) g_cnt[i] = 0;
}
__global__ void k_cnt(const int* __restrict__ dst) {
    int e = blockIdx.x * 256 + threadIdx.x;
    if (e < NE) atomicAdd(&g_cnt[dst[e]], 1);
}
// block-wise inclusive scan, 1024/block
__global__ __launch_bounds__(1024) void k_scan1() {
    __shared__ int sh[1024];
    int i = blockIdx.x * 1024 + threadIdx.x;
    int v = (i < NN) ? g_cnt[i] : 0;
    sh[threadIdx.x] = v;
    __syncthreads();
#pragma unroll
    for (int off = 1; off < 1024; off <<= 1) {
        int t = (threadIdx.x >= off) ? sh[threadIdx.x - off] : 0;
        __syncthreads();
        sh[threadIdx.x] += t;
        __syncthreads();
    }
    if (i < NN) g_tmp[i] = sh[threadIdx.x];
    if (threadIdx.x == 1023) g_bsum[blockIdx.x] = sh[1023];
}
__global__ __launch_bounds__(128) void k_scan2() {
    __shared__ int sh[128];
    int t = threadIdx.x;
    int v = (t < NBLK) ? g_bsum[t] : 0;
    sh[t] = v;
    __syncthreads();
#pragma unroll
    for (int off = 1; off < 128; off <<= 1) {
        int u = (t >= off) ? sh[t - off] : 0;
        __syncthreads();
        sh[t] += u;
        __syncthreads();
    }
    if (t < NBLK) g_bsum[t] = sh[t] - v;    // exclusive
}
__global__ void k_scan3() {
    int i = blockIdx.x * 256 + threadIdx.x;
    if (i < NN) {
        int c = g_cnt[i];
        int excl = g_tmp[i] - c + g_bsum[i >> 10];
        g_row[i] = excl;
        g_cur[i] = excl;
        g_dinv[i] = rsqrtf((float)(c + 1));   // +1 self loop
    }
    if (i == 0) g_row[NN] = NE;
}
__global__ void k_bucket(const int* __restrict__ src, const int* __restrict__ dst) {
    int e = blockIdx.x * 256 + threadIdx.x;
    if (e >= NE) return;
    int pos = atomicAdd(&g_cur[dst[e]], 1);
    g_csrc[pos] = src[e];
}

// ---------------- SGEMM: hS = dinv * (A[nrows,128] @ B[128,128]) -------------
// BM=128, BN=128, BK=16, 256 threads, 8x8 register tile per thread.
__global__ __launch_bounds__(256) void k_gemm(const float* __restrict__ Ax,
                                              const float* __restrict__ B,
                                              int use_x, int nrows) {
    __shared__ float As[16][128];   // [k][row]
    __shared__ float Bs[16][128];   // [k][col]
    const float* A = use_x ? Ax : (const float*)g_acc;

    float acc[8][8];
#pragma unroll
    for (int m = 0; m < 8; m++)
#pragma unroll
        for (int n = 0; n < 8; n++) acc[m][n] = 0.f;

    const int tid = threadIdx.x;
    const int tx = tid & 15;        // cols tx*8..tx*8+7
    const int ty = tid >> 4;        // rows ty*8..ty*8+7
    const int rowBase = blockIdx.x * 128;

    for (int k0 = 0; k0 < 128; k0 += 16) {
#pragma unroll
        for (int i = 0; i < 2; i++) {
            int f = tid + i * 256;
            int r = f >> 2;
            int c = (f & 3) * 4;
            int gr = rowBase + r;
            float4 v = make_float4(0.f, 0.f, 0.f, 0.f);
            if (gr < nrows) v = *(const float4*)(A + (size_t)gr * H + k0 + c);
            As[c + 0][r] = v.x; As[c + 1][r] = v.y;
            As[c + 2][r] = v.z; As[c + 3][r] = v.w;
        }
#pragma unroll
        for (int i = 0; i < 2; i++) {
            int f = tid + i * 256;
            int r = f >> 5;
            int c = (f & 31) * 4;
            *(float4*)&Bs[r][c] = *(const float4*)(B + (size_t)(k0 + r) * H + c);
        }
        __syncthreads();

#pragma unroll
        for (int k = 0; k < 16; k++) {
            float rm[8], rn[8];
#pragma unroll
            for (int m = 0; m < 8; m++) rm[m] = As[k][ty * 8 + m];
#pragma unroll
            for (int n = 0; n < 8; n++) rn[n] = Bs[k][tx * 8 + n];
#pragma unroll
            for (int m = 0; m < 8; m++)
#pragma unroll
                for (int n = 0; n < 8; n++) acc[m][n] += rm[m] * rn[n];
        }
        __syncthreads();
    }

#pragma unroll
    for (int m = 0; m < 8; m++) {
        int gr = rowBase + ty * 8 + m;
        if (gr < nrows) {
            float di = g_dinv[gr];
#pragma unroll
            for (int n = 0; n < 8; n += 4) {
                *(float4*)(g_hW + (size_t)gr * H + tx * 8 + n) =
                    make_float4(di * acc[m][n],     di * acc[m][n + 1],
                                di * acc[m][n + 2], di * acc[m][n + 3]);
            }
        }
    }
}

// ---------------- CSR gather: acc[i] = relu(dinv[i]*(sum hS[src] + hS[i]) + b)
// one warp per node, lane q owns dims 4q..4q+3
__global__ __launch_bounds__(256) void k_gather(const float* __restrict__ b) {
    int idx = blockIdx.x * 256 + threadIdx.x;
    int i = idx >> 5;
    if (i >= NN) return;
    int q = idx & 31;

    int lo = __ldg(g_row + i);
    int hi = __ldg(g_row + i + 1);

    // self loop term
    float4 acc = __ldg((const float4*)(g_hW + (size_t)i * H) + q);

    int j = lo;
    for (; j + 4 <= hi; j += 4) {
        int s0 = __ldg(g_csrc + j);
        int s1 = __ldg(g_csrc + j + 1);
        int s2 = __ldg(g_csrc + j + 2);
        int s3 = __ldg(g_csrc + j + 3);
        float4 v0 = __ldg((const float4*)(g_hW + (size_t)s0 * H) + q);
        float4 v1 = __ldg((const float4*)(g_hW + (size_t)s1 * H) + q);
        float4 v2 = __ldg((const float4*)(g_hW + (size_t)s2 * H) + q);
        float4 v3 = __ldg((const float4*)(g_hW + (size_t)s3 * H) + q);
        acc.x += v0.x + v1.x + v2.x + v3.x;
        acc.y += v0.y + v1.y + v2.y + v3.y;
        acc.z += v0.z + v1.z + v2.z + v3.z;
        acc.w += v0.w + v1.w + v2.w + v3.w;
    }
    for (; j < hi; j++) {
        int s = __ldg(g_csrc + j);
        float4 v = __ldg((const float4*)(g_hW + (size_t)s * H) + q);
        acc.x += v.x; acc.y += v.y; acc.z += v.z; acc.w += v.w;
    }

    float di = __ldg(g_dinv + i);
    float4 bb = __ldg((const float4*)b + q);
    float4 r;
    r.x = fmaxf(fmaf(di, acc.x, bb.x), 0.f);
    r.y = fmaxf(fmaf(di, acc.y, bb.y), 0.f);
    r.z = fmaxf(fmaf(di, acc.z, bb.z), 0.f);
    r.w = fmaxf(fmaf(di, acc.w, bb.w), 0.f);
    *((float4*)(g_acc + (size_t)i * H) + q) = r;
}

// ---------------- mean pool per graph (batch is sorted) ----------------------
__device__ __forceinline__ int lower_bound_i(const int* a, int n, int v) {
    int lo = 0, hi = n;
    while (lo < hi) { int m = (lo + hi) >> 1; if (a[m] < v) lo = m + 1; else hi = m; }
    return lo;
}
__global__ void k_pool(const int* __restrict__ batch) {
    int g = blockIdx.x, d = threadIdx.x;
    __shared__ int lohi[2];
    if (d == 0) lohi[0] = lower_bound_i(batch, NN, g);
    if (d == 1) lohi[1] = lower_bound_i(batch, NN, g + 1);
    __syncthreads();
    int lo = lohi[0], hi = lohi[1];
    float s = 0.f;
    for (int i = lo; i < hi; i++) s += g_acc[(size_t)i * H + d];
    float c = (float)(hi - lo);
    g_gemb[g * H + d] = s / fmaxf(c, 1.f);
}

// ---------------- zero agg ----------------------------------------------------
__global__ void k_zero_agg() {
    int i = blockIdx.x * 256 + threadIdx.x;
    if (i < NS * H) g_agg[i] = 0.f;
}

// ---------------- DeepSets psi + segment-sum into agg ------------------------
__global__ void k_psi(const int* __restrict__ setb,
                      const float* __restrict__ W1, const float* __restrict__ b1,
                      const float* __restrict__ W2, const float* __restrict__ b2) {
    int g = blockIdx.x, d = threadIdx.x;
    __shared__ float v[H], t[H];
    v[d] = g_gemb[g * H + d];
    __syncthreads();
    float s = b1[d];
#pragma unroll 8
    for (int k = 0; k < H; k++) s += v[k] * W1[k * H + d];
    t[d] = fmaxf(s, 0.f);
    __syncthreads();
    float s2 = b2[d];
#pragma unroll 8
    for (int k = 0; k < H; k++) s2 += t[k] * W2[k * H + d];
    atomicAdd(&g_agg[setb[g] * H + d], tanhf(s2));
}

// ---------------- phi head: out = relu(agg@phiW1+b1)@phiW2+b2 ----------------
__global__ void k_final(const float* __restrict__ W1, const float* __restrict__ b1,
                        const float* __restrict__ W2, const float* __restrict__ b2,
                        float* __restrict__ out) {
    int s = blockIdx.x, d = threadIdx.x;
    __shared__ float a[H], t[H];
    a[d] = g_agg[s * H + d];
    __syncthreads();
    float acc = b1[d];
#pragma unroll 8
    for (int k = 0; k < H; k++) acc += a[k] * W1[k * H + d];
    t[d] = fmaxf(acc, 0.f);
    __syncthreads();
    if (d < NC) {
        float o = b2[d];
#pragma unroll 8
        for (int k = 0; k < H; k++) o += t[k] * W2[k * NC + d];
        out[s * NC + d] = o;
    }
}

// ---------------- launch ------------------------------------------------------
extern "C" void kernel_launch(void* const* d_in, const int* in_sizes, int n_in,
                              void* d_out, int out_size) {
    const float* x     = (const float*)d_in[0];
    const int*   ei    = (const int*)  d_in[1];
    const int*   batch = (const int*)  d_in[2];
    const int*   setb  = (const int*)  d_in[3];
    const float* W1    = (const float*)d_in[4];
    const float* b1    = (const float*)d_in[5];
    const float* W2    = (const float*)d_in[6];
    const float* b2    = (const float*)d_in[7];
    const float* W3    = (const float*)d_in[8];
    const float* b3    = (const float*)d_in[9];
    const float* psiW1 = (const float*)d_in[10];
    const float* psib1 = (const float*)d_in[11];
    const float* psiW2 = (const float*)d_in[12];
    const float* psib2 = (const float*)d_in[13];
    const float* phiW1 = (const float*)d_in[14];
    const float* phib1 = (const float*)d_in[15];
    const float* phiW2 = (const float*)d_in[16];
    const float* phib2 = (const float*)d_in[17];
    float* out = (float*)d_out;

    const int* src = ei;          // edge_index[0]
    const int* dst = ei + NE;     // edge_index[1]

    // CSR build (per call; deterministic up to within-row ordering)
    k_zero_cnt<<<(NN + 255) / 256, 256>>>();
    k_cnt     <<<(NE + 255) / 256, 256>>>(dst);
    k_scan1   <<<NBLK, 1024>>>();
    k_scan2   <<<1, 128>>>();
    k_scan3   <<<(NN + 255) / 256, 256>>>();
    k_bucket  <<<(NE + 255) / 256, 256>>>(src, dst);

    const float* Ws[3] = {W1, W2, W3};
    const float* bs[3] = {b1, b2, b3};
    for (int l = 0; l < 3; l++) {
        k_gemm  <<<NPAD / 128, 256>>>(x, Ws[l], l == 0 ? 1 : 0, NN);
        k_gather<<<(NN * 32 + 255) / 256, 256>>>(bs[l]);
    }

    k_pool    <<<NG, H>>>(batch);
    k_zero_agg<<<(NS * H + 255) / 256, 256>>>();
    k_psi     <<<NG, H>>>(setb, psiW1, psib1, psiW2, psib2);
    k_final   <<<NS, H>>>(phiW1, phib1, phiW2, phib2, out);
}

// round 5
// speedup vs baseline: 3.3408x; 1.0155x over previous
#include <cuda_runtime.h>
#include <cuda_fp16.h>
#include <cstdint>

#define NN   100000      // nodes
#define NPAD 100096      // 782 * 128
#define NE   1600000     // edges
#define H    128
#define NG   2000        // graphs
#define NS   200         // sets
#define NC   10          // classes
#define NBLK 98          // ceil(NN/1024) scan blocks

// ---------------- scratch (static device globals; no allocation) -------------
__device__ __align__(16) int   g_cnt [NN];
__device__ __align__(16) int   g_tmp [NN];
__device__ __align__(16) int   g_bsum[128];
__device__ __align__(16) int   g_row [NN + 1];
__device__ __align__(16) int   g_cur [NN];
__device__ __align__(16) int   g_csrc[NE];
__device__ __align__(16) float g_dinv[NN];
__device__ __align__(16) float g_hW [(size_t)NPAD * H];   // dinv-scaled GEMM out (fp32)
__device__ __align__(16) float g_acc[(size_t)NPAD * H];   // layer output
__device__ __align__(16) float g_gemb[NG * H];
__device__ __align__(16) float g_agg [NS * H];

// ---------------- CSR build ---------------------------------------------------
__global__ void k_zero_cnt() {
    int i = blockIdx.x * 256 + threadIdx.x;
    if (i < NN) g_cnt[i] = 0;
}
__global__ void k_cnt(const int* __restrict__ dst) {
    int e = blockIdx.x * 256 + threadIdx.x;
    if (e < NE) atomicAdd(&g_cnt[dst[e]], 1);
}
__global__ __launch_bounds__(1024) void k_scan1() {
    __shared__ int sh[1024];
    int i = blockIdx.x * 1024 + threadIdx.x;
    int v = (i < NN) ? g_cnt[i] : 0;
    sh[threadIdx.x] = v;
    __syncthreads();
#pragma unroll
    for (int off = 1; off < 1024; off <<= 1) {
        int t = (threadIdx.x >= off) ? sh[threadIdx.x - off] : 0;
        __syncthreads();
        sh[threadIdx.x] += t;
        __syncthreads();
    }
    if (i < NN) g_tmp[i] = sh[threadIdx.x];
    if (threadIdx.x == 1023) g_bsum[blockIdx.x] = sh[1023];
}
__global__ __launch_bounds__(128) void k_scan2() {
    __shared__ int sh[128];
    int t = threadIdx.x;
    int v = (t < NBLK) ? g_bsum[t] : 0;
    sh[t] = v;
    __syncthreads();
#pragma unroll
    for (int off = 1; off < 128; off <<= 1) {
        int u = (t >= off) ? sh[t - off] : 0;
        __syncthreads();
        sh[t] += u;
        __syncthreads();
    }
    if (t < NBLK) g_bsum[t] = sh[t] - v;    // exclusive
}
__global__ void k_scan3() {
    int i = blockIdx.x * 256 + threadIdx.x;
    if (i < NN) {
        int c = g_cnt[i];
        int excl = g_tmp[i] - c + g_bsum[i >> 10];
        g_row[i] = excl;
        g_cur[i] = excl;
        g_dinv[i] = rsqrtf((float)(c + 1));   // +1 self loop
    }
    if (i == 0) g_row[NN] = NE;
}
__global__ void k_bucket(const int* __restrict__ src, const int* __restrict__ dst) {
    int e = blockIdx.x * 256 + threadIdx.x;
    if (e >= NE) return;
    int pos = atomicAdd(&g_cur[dst[e]], 1);
    g_csrc[pos] = src[e];
}

// ---------------- tensor-core GEMM with fp16x3 split -------------------------
// hS(fp32) = dinv * (A[nrows,128] @ B[128,128]); error ~2^-22 per element.
__device__ __forceinline__ void mma16816(float* d, uint32_t a0, uint32_t a1,
                                         uint32_t a2, uint32_t a3,
                                         uint32_t b0, uint32_t b1) {
    asm volatile(
        "mma.sync.aligned.m16n8k16.row.col.f32.f16.f16.f32 "
        "{%0,%1,%2,%3}, {%4,%5,%6,%7}, {%8,%9}, {%0,%1,%2,%3};"
        : "+f"(d[0]), "+f"(d[1]), "+f"(d[2]), "+f"(d[3])
        : "r"(a0), "r"(a1), "r"(a2), "r"(a3), "r"(b0), "r"(b1));
}
__device__ __forceinline__ void fsplit(float a, __half& h, __half& l) {
    h = __float2half_rn(a);
    l = __float2half_rn(a - __half2float(h));
}

#define BKP 40   // padded k-stride in halves (80B row -> conflict-free frag loads)

__global__ __launch_bounds__(256) void k_gemm_tc(const float* __restrict__ Ax,
                                                 const float* __restrict__ Bm,
                                                 int use_x, int nrows) {
    __shared__ __half Ah[128][BKP], Al[128][BKP];   // [row][k]
    __shared__ __half Bh[128][BKP], Bl[128][BKP];   // transposed: [n][k]
    const float* A = use_x ? Ax : (const float*)g_acc;

    const int tid  = threadIdx.x;
    const int lane = tid & 31;
    const int w    = tid >> 5;
    const int g    = lane >> 2;   // 0..7
    const int t    = lane & 3;    // 0..3
    const int wm   = w & 3;       // 4 warps along M (32 rows each)
    const int wn   = w >> 2;      // 2 warps along N (64 cols each)
    const int rowBase = blockIdx.x * 128;

    float d[2][8][4];
#pragma unroll
    for (int mt = 0; mt < 2; mt++)
#pragma unroll
        for (int nt = 0; nt < 8; nt++)
#pragma unroll
            for (int i = 0; i < 4; i++) d[mt][nt][i] = 0.f;

    for (int k0 = 0; k0 < 128; k0 += 32) {
        __syncthreads();
        // A tile 128x32 fp32 -> hi/lo halves
#pragma unroll
        for (int i = 0; i < 4; i++) {
            int id = tid + i * 256;           // 0..1023 float4s
            int r  = id >> 3;
            int c4 = (id & 7) * 4;
            int gr = rowBase + r;
            float4 v = make_float4(0.f, 0.f, 0.f, 0.f);
            if (gr < nrows) v = *(const float4*)(A + (size_t)gr * H + k0 + c4);
            __half h0, l0, h1, l1, h2, l2, h3, l3;
            fsplit(v.x, h0, l0); fsplit(v.y, h1, l1);
            fsplit(v.z, h2, l2); fsplit(v.w, h3, l3);
            Ah[r][c4 + 0] = h0; Ah[r][c4 + 1] = h1; Ah[r][c4 + 2] = h2; Ah[r][c4 + 3] = h3;
            Al[r][c4 + 0] = l0; Al[r][c4 + 1] = l1; Al[r][c4 + 2] = l2; Al[r][c4 + 3] = l3;
        }
        // B tile 32x128 fp32 -> transposed hi/lo halves [n][k]
#pragma unroll
        for (int i = 0; i < 4; i++) {
            int id = tid + i * 256;
            int kk = id >> 5;
            int n4 = (id & 31) * 4;
            float4 v = *(const float4*)(Bm + (size_t)(k0 + kk) * H + n4);
            __half h, l;
            fsplit(v.x, h, l); Bh[n4 + 0][kk] = h; Bl[n4 + 0][kk] = l;
            fsplit(v.y, h, l); Bh[n4 + 1][kk] = h; Bl[n4 + 1][kk] = l;
            fsplit(v.z, h, l); Bh[n4 + 2][kk] = h; Bl[n4 + 2][kk] = l;
            fsplit(v.w, h, l); Bh[n4 + 3][kk] = h; Bl[n4 + 3][kk] = l;
        }
        __syncthreads();

#pragma unroll
        for (int kt = 0; kt < 2; kt++) {
            int ks = kt * 16;
            uint32_t bh0[8], bh1[8], bl0[8], bl1[8];
#pragma unroll
            for (int nt = 0; nt < 8; nt++) {
                int n = wn * 64 + nt * 8 + g;
                bh0[nt] = *(const uint32_t*)&Bh[n][ks + 2 * t];
                bh1[nt] = *(const uint32_t*)&Bh[n][ks + 2 * t + 8];
                bl0[nt] = *(const uint32_t*)&Bl[n][ks + 2 * t];
                bl1[nt] = *(const uint32_t*)&Bl[n][ks + 2 * t + 8];
            }
#pragma unroll
            for (int mt = 0; mt < 2; mt++) {
                int m = wm * 32 + mt * 16;
                uint32_t ah0 = *(const uint32_t*)&Ah[m + g][ks + 2 * t];
                uint32_t ah1 = *(const uint32_t*)&Ah[m + g + 8][ks + 2 * t];
                uint32_t ah2 = *(const uint32_t*)&Ah[m + g][ks + 2 * t + 8];
                uint32_t ah3 = *(const uint32_t*)&Ah[m + g + 8][ks + 2 * t + 8];
                uint32_t al0 = *(const uint32_t*)&Al[m + g][ks + 2 * t];
                uint32_t al1 = *(const uint32_t*)&Al[m + g + 8][ks + 2 * t];
                uint32_t al2 = *(const uint32_t*)&Al[m + g][ks + 2 * t + 8];
                uint32_t al3 = *(const uint32_t*)&Al[m + g + 8][ks + 2 * t + 8];
#pragma unroll
                for (int nt = 0; nt < 8; nt++) {
                    mma16816(d[mt][nt], al0, al1, al2, al3, bh0[nt], bh1[nt]);
                    mma16816(d[mt][nt], ah0, ah1, ah2, ah3, bl0[nt], bl1[nt]);
                    mma16816(d[mt][nt], ah0, ah1, ah2, ah3, bh0[nt], bh1[nt]);
                }
            }
        }
    }

    // epilogue: dinv scale, fp32 store
#pragma unroll
    for (int mt = 0; mt < 2; mt++) {
        int r0 = rowBase + wm * 32 + mt * 16 + g;
        int r1 = r0 + 8;
        float di0 = (r0 < nrows) ? g_dinv[r0] : 0.f;
        float di1 = (r1 < nrows) ? g_dinv[r1] : 0.f;
#pragma unroll
        for (int nt = 0; nt < 8; nt++) {
            int c = wn * 64 + nt * 8 + 2 * t;
            if (r0 < nrows) {
                g_hW[(size_t)r0 * H + c]     = di0 * d[mt][nt][0];
                g_hW[(size_t)r0 * H + c + 1] = di0 * d[mt][nt][1];
            }
            if (r1 < nrows) {
                g_hW[(size_t)r1 * H + c]     = di1 * d[mt][nt][2];
                g_hW[(size_t)r1 * H + c + 1] = di1 * d[mt][nt][3];
            }
        }
    }
}

// ---------------- CSR gather: acc[i] = relu(dinv[i]*(sum hS[src] + hS[i]) + b)
__global__ __launch_bounds__(256) void k_gather(const float* __restrict__ b) {
    int idx = blockIdx.x * 256 + threadIdx.x;
    int i = idx >> 5;
    if (i >= NN) return;
    int q = idx & 31;

    int lo = __ldg(g_row + i);
    int hi = __ldg(g_row + i + 1);

    float4 acc = __ldg((const float4*)(g_hW + (size_t)i * H) + q);   // self loop

    int j = lo;
    for (; j + 4 <= hi; j += 4) {
        int s0 = __ldg(g_csrc + j);
        int s1 = __ldg(g_csrc + j + 1);
        int s2 = __ldg(g_csrc + j + 2);
        int s3 = __ldg(g_csrc + j + 3);
        float4 v0 = __ldg((const float4*)(g_hW + (size_t)s0 * H) + q);
        float4 v1 = __ldg((const float4*)(g_hW + (size_t)s1 * H) + q);
        float4 v2 = __ldg((const float4*)(g_hW + (size_t)s2 * H) + q);
        float4 v3 = __ldg((const float4*)(g_hW + (size_t)s3 * H) + q);
        acc.x += v0.x + v1.x + v2.x + v3.x;
        acc.y += v0.y + v1.y + v2.y + v3.y;
        acc.z += v0.z + v1.z + v2.z + v3.z;
        acc.w += v0.w + v1.w + v2.w + v3.w;
    }
    for (; j < hi; j++) {
        int s = __ldg(g_csrc + j);
        float4 v = __ldg((const float4*)(g_hW + (size_t)s * H) + q);
        acc.x += v.x; acc.y += v.y; acc.z += v.z; acc.w += v.w;
    }

    float di = __ldg(g_dinv + i);
    float4 bb = __ldg((const float4*)b + q);
    float4 r;
    r.x = fmaxf(fmaf(di, acc.x, bb.x), 0.f);
    r.y = fmaxf(fmaf(di, acc.y, bb.y), 0.f);
    r.z = fmaxf(fmaf(di, acc.z, bb.z), 0.f);
    r.w = fmaxf(fmaf(di, acc.w, bb.w), 0.f);
    *((float4*)(g_acc + (size_t)i * H) + q) = r;
}

// ---------------- mean pool per graph (batch is sorted) ----------------------
__device__ __forceinline__ int lower_bound_i(const int* a, int n, int v) {
    int lo = 0, hi = n;
    while (lo < hi) { int m = (lo + hi) >> 1; if (a[m] < v) lo = m + 1; else hi = m; }
    return lo;
}
__global__ void k_pool(const int* __restrict__ batch) {
    int g = blockIdx.x, d = threadIdx.x;
    __shared__ int lohi[2];
    if (d == 0) lohi[0] = lower_bound_i(batch, NN, g);
    if (d == 1) lohi[1] = lower_bound_i(batch, NN, g + 1);
    __syncthreads();
    int lo = lohi[0], hi = lohi[1];
    float s = 0.f;
    for (int i = lo; i < hi; i++) s += g_acc[(size_t)i * H + d];
    float c = (float)(hi - lo);
    g_gemb[g * H + d] = s / fmaxf(c, 1.f);
}

// ---------------- zero agg ----------------------------------------------------
__global__ void k_zero_agg() {
    int i = blockIdx.x * 256 + threadIdx.x;
    if (i < NS * H) g_agg[i] = 0.f;
}

// ---------------- DeepSets psi + segment-sum into agg ------------------------
__global__ void k_psi(const int* __restrict__ setb,
                      const float* __restrict__ W1, const float* __restrict__ b1,
                      const float* __restrict__ W2, const float* __restrict__ b2) {
    int g = blockIdx.x, d = threadIdx.x;
    __shared__ float v[H], t[H];
    v[d] = g_gemb[g * H + d];
    __syncthreads();
    float s = b1[d];
#pragma unroll 8
    for (int k = 0; k < H; k++) s += v[k] * W1[k * H + d];
    t[d] = fmaxf(s, 0.f);
    __syncthreads();
    float s2 = b2[d];
#pragma unroll 8
    for (int k = 0; k < H; k++) s2 += t[k] * W2[k * H + d];
    atomicAdd(&g_agg[setb[g] * H + d], tanhf(s2));
}

// ---------------- phi head: out = relu(agg@phiW1+b1)@phiW2+b2 ----------------
__global__ void k_final(const float* __restrict__ W1, const float* __restrict__ b1,
                        const float* __restrict__ W2, const float* __restrict__ b2,
                        float* __restrict__ out) {
    int s = blockIdx.x, d = threadIdx.x;
    __shared__ float a[H], t[H];
    a[d] = g_agg[s * H + d];
    __syncthreads();
    float acc = b1[d];
#pragma unroll 8
    for (int k = 0; k < H; k++) acc += a[k] * W1[k * H + d];
    t[d] = fmaxf(acc, 0.f);
    __syncthreads();
    if (d < NC) {
        float o = b2[d];
#pragma unroll 8
        for (int k = 0; k < H; k++) o += t[k] * W2[k * NC + d];
        out[s * NC + d] = o;
    }
}

// ---------------- launch ------------------------------------------------------
extern "C" void kernel_launch(void* const* d_in, const int* in_sizes, int n_in,
                              void* d_out, int out_size) {
    const float* x     = (const float*)d_in[0];
    const int*   ei    = (const int*)  d_in[1];
    const int*   batch = (const int*)  d_in[2];
    const int*   setb  = (const int*)  d_in[3];
    const float* W1    = (const float*)d_in[4];
    const float* b1    = (const float*)d_in[5];
    const float* W2    = (const float*)d_in[6];
    const float* b2    = (const float*)d_in[7];
    const float* W3    = (const float*)d_in[8];
    const float* b3    = (const float*)d_in[9];
    const float* psiW1 = (const float*)d_in[10];
    const float* psib1 = (const float*)d_in[11];
    const float* psiW2 = (const float*)d_in[12];
    const float* psib2 = (const float*)d_in[13];
    const float* phiW1 = (const float*)d_in[14];
    const float* phib1 = (const float*)d_in[15];
    const float* phiW2 = (const float*)d_in[16];
    const float* phib2 = (const float*)d_in[17];
    float* out = (float*)d_out;

    const int* src = ei;          // edge_index[0]
    const int* dst = ei + NE;     // edge_index[1]

    // CSR build
    k_zero_cnt<<<(NN + 255) / 256, 256>>>();
    k_cnt     <<<(NE + 255) / 256, 256>>>(dst);
    k_scan1   <<<NBLK, 1024>>>();
    k_scan2   <<<1, 128>>>();
    k_scan3   <<<(NN + 255) / 256, 256>>>();
    k_bucket  <<<(NE + 255) / 256, 256>>>(src, dst);

    const float* Ws[3] = {W1, W2, W3};
    const float* bs[3] = {b1, b2, b3};
    for (int l = 0; l < 3; l++) {
        k_gemm_tc<<<NPAD / 128, 256>>>(x, Ws[l], l == 0 ? 1 : 0, NN);
        k_gather <<<(NN * 32 + 255) / 256, 256>>>(bs[l]);
    }

    k_pool    <<<NG, H>>>(batch);
    k_zero_agg<<<(NS * H + 255) / 256, 256>>>();
    k_psi     <<<NG, H>>>(setb, psiW1, psib1, psiW2, psib2);
    k_final   <<<NS, H>>>(phiW1, phib1, phiW2, phib2, out);
}